// round 4
// baseline (speedup 1.0000x reference)
#include <cuda_runtime.h>

#define N_TOKENS  131072
#define CODE_DIM  64
#define NUM_CODES 1024

// ---------------- device scratch (no allocations allowed) ----------------
__device__ float g_counts[NUM_CODES];
__device__ float g_dw[NUM_CODES * CODE_DIM];
__device__ float g_loss;
__device__ float g_ncs[NUM_CODES];
__device__ float g_n;

// ---------------- zero scratch each launch (graph-capturable) ----------------
__global__ void vq_zero() {
    int i = blockIdx.x * blockDim.x + threadIdx.x;
    if (i < NUM_CODES * CODE_DIM) g_dw[i] = 0.0f;
    if (i < NUM_CODES) g_counts[i] = 0.0f;
    if (i == 0) g_loss = 0.0f;
}

// ---------------- main: distances + argmin + quantize + scatter stats ----------------
// Block: 128 tokens x all 1024 codes (8 tiles of 128 codes), K = 64 resident.
// 256 threads as 16x16, each owns an 8x8 (token x code) micro-tile.
__global__ __launch_bounds__(256, 2)
void vq_main(const float* __restrict__ z, const float* __restrict__ codebook,
             float* __restrict__ out_q, float* __restrict__ out_idx)
{
    extern __shared__ float smem[];
    float* zsT  = smem;                 // [64][128]  z tile, K-major
    float* csT  = zsT + 64 * 128;       // [64][128]  codebook tile, K-major
    float* zz_s = csT + 64 * 128;       // [128]      ||z_i||^2
    float* cc_s = zz_s + 128;           // [128]      ||c_k||^2 (current tile)
    float* red_d = cc_s + 128;          // [128][16]  per-tx best d2
    int*   red_i = (int*)(red_d + 128 * 16); // [128][16] per-tx best idx

    const int tid = threadIdx.x;
    const int tx = tid & 15;
    const int ty = tid >> 4;
    const int token0 = blockIdx.x * 128;

    // ---- load z tile transposed into smem + row sumsq ----
    {
        int r = tid >> 1, h = tid & 1;   // 2 threads per token row
        const float4* zp = reinterpret_cast<const float4*>(
            z + (size_t)(token0 + r) * CODE_DIM) + h * 8;
        float sq = 0.0f;
        #pragma unroll
        for (int v = 0; v < 8; v++) {
            float4 t = zp[v];
            int k = h * 32 + v * 4;
            zsT[(k + 0) * 128 + r] = t.x;
            zsT[(k + 1) * 128 + r] = t.y;
            zsT[(k + 2) * 128 + r] = t.z;
            zsT[(k + 3) * 128 + r] = t.w;
            sq += t.x * t.x; sq += t.y * t.y; sq += t.z * t.z; sq += t.w * t.w;
        }
        sq += __shfl_xor_sync(0xffffffffu, sq, 1);
        if (h == 0) zz_s[r] = sq;
    }
    __syncthreads();

    float zzv[8];
    #pragma unroll
    for (int i = 0; i < 8; i++) zzv[i] = zz_s[ty * 8 + i];

    float best[8];
    int   bidx[8];
    #pragma unroll
    for (int i = 0; i < 8; i++) { best[i] = 3.4e38f; bidx[i] = 0; }

    for (int ct = 0; ct < 8; ct++) {
        // ---- load codebook tile transposed + row sumsq ----
        {
            int r = tid >> 1, h = tid & 1;
            const float4* cp = reinterpret_cast<const float4*>(
                codebook + (size_t)(ct * 128 + r) * CODE_DIM) + h * 8;
            float sq = 0.0f;
            #pragma unroll
            for (int v = 0; v < 8; v++) {
                float4 t = cp[v];
                int k = h * 32 + v * 4;
                csT[(k + 0) * 128 + r] = t.x;
                csT[(k + 1) * 128 + r] = t.y;
                csT[(k + 2) * 128 + r] = t.z;
                csT[(k + 3) * 128 + r] = t.w;
                sq += t.x * t.x; sq += t.y * t.y; sq += t.z * t.z; sq += t.w * t.w;
            }
            sq += __shfl_xor_sync(0xffffffffu, sq, 1);
            if (h == 0) cc_s[r] = sq;
        }
        __syncthreads();

        float acc[8][8];
        #pragma unroll
        for (int i = 0; i < 8; i++)
            #pragma unroll
            for (int j = 0; j < 8; j++) acc[i][j] = 0.0f;

        #pragma unroll 8
        for (int k = 0; k < 64; k++) {
            float a[8], b[8];
            float4 a0 = *reinterpret_cast<const float4*>(&zsT[k * 128 + ty * 8]);
            float4 a1 = *reinterpret_cast<const float4*>(&zsT[k * 128 + ty * 8 + 4]);
            float4 b0 = *reinterpret_cast<const float4*>(&csT[k * 128 + tx * 8]);
            float4 b1 = *reinterpret_cast<const float4*>(&csT[k * 128 + tx * 8 + 4]);
            a[0] = a0.x; a[1] = a0.y; a[2] = a0.z; a[3] = a0.w;
            a[4] = a1.x; a[5] = a1.y; a[6] = a1.z; a[7] = a1.w;
            b[0] = b0.x; b[1] = b0.y; b[2] = b0.z; b[3] = b0.w;
            b[4] = b1.x; b[5] = b1.y; b[6] = b1.z; b[7] = b1.w;
            #pragma unroll
            for (int i = 0; i < 8; i++)
                #pragma unroll
                for (int j = 0; j < 8; j++)
                    acc[i][j] += a[i] * b[j];
        }

        // d2 = (zz - 2*dot) + cc, matching reference rounding order.
        // Codes scanned in ascending index order; strict < keeps the earliest (argmin tie rule).
        #pragma unroll
        for (int j = 0; j < 8; j++) {
            float cc = cc_s[tx * 8 + j];
            int code = ct * 128 + tx * 8 + j;
            #pragma unroll
            for (int i = 0; i < 8; i++) {
                float d2 = (zzv[i] - 2.0f * acc[i][j]) + cc;
                if (d2 < best[i]) { best[i] = d2; bidx[i] = code; }
            }
        }
        __syncthreads();   // before next tile overwrites csT/cc_s
    }

    // ---- cross-thread (tx) argmin reduction per token ----
    #pragma unroll
    for (int i = 0; i < 8; i++) {
        red_d[(ty * 8 + i) * 16 + tx] = best[i];
        red_i[(ty * 8 + i) * 16 + tx] = bidx[i];
    }
    __syncthreads();

    float lsum = 0.0f;
    if (tid < 128) {
        int t = tid;
        float bd = red_d[t * 16];
        int   bi = red_i[t * 16];
        #pragma unroll
        for (int j = 1; j < 16; j++) {
            float d = red_d[t * 16 + j];
            int  ix = red_i[t * 16 + j];
            if (d < bd || (d == bd && ix < bi)) { bd = d; bi = ix; }
        }
        int token = token0 + t;
        out_idx[token] = (float)bi;
        atomicAdd(&g_counts[bi], 1.0f);

        const float4* cb = reinterpret_cast<const float4*>(codebook + (size_t)bi * CODE_DIM);
        float4* qo = reinterpret_cast<float4*>(out_q + (size_t)token * CODE_DIM);
        #pragma unroll
        for (int v = 0; v < 16; v++) {
            float4 q = cb[v];
            int k = v * 4;
            float z0 = zsT[(k + 0) * 128 + t];
            float z1 = zsT[(k + 1) * 128 + t];
            float z2 = zsT[(k + 2) * 128 + t];
            float z3 = zsT[(k + 3) * 128 + t];
            float d0 = z0 - q.x, d1 = z1 - q.y, d2 = z2 - q.z, d3 = z3 - q.w;
            lsum += d0 * d0; lsum += d1 * d1; lsum += d2 * d2; lsum += d3 * d3;
            qo[v] = q;
            atomicAdd(&g_dw[bi * CODE_DIM + k + 0], z0);
            atomicAdd(&g_dw[bi * CODE_DIM + k + 1], z1);
            atomicAdd(&g_dw[bi * CODE_DIM + k + 2], z2);
            atomicAdd(&g_dw[bi * CODE_DIM + k + 3], z3);
        }
    }

    // ---- block reduction of commitment-loss partial (all 256 threads) ----
    #pragma unroll
    for (int o = 16; o > 0; o >>= 1) lsum += __shfl_down_sync(0xffffffffu, lsum, o);
    __shared__ float lpart[8];
    if ((tid & 31) == 0) lpart[tid >> 5] = lsum;
    __syncthreads();
    if (tid == 0) {
        float s = 0.0f;
        #pragma unroll
        for (int w = 0; w < 8; w++) s += lpart[w];
        atomicAdd(&g_loss, s);
    }
}

// ---------------- finalize 1: new_cluster_size + its sum ----------------
__global__ void vq_final_cs(const float* __restrict__ cluster_size,
                            float* __restrict__ out_cs)
{
    int t = threadIdx.x;  // 1024 threads, 1 block
    float ncs = 0.99f * cluster_size[t] + 0.01f * g_counts[t];
    out_cs[t] = ncs;
    g_ncs[t] = ncs;

    float s = ncs;
    #pragma unroll
    for (int o = 16; o > 0; o >>= 1) s += __shfl_down_sync(0xffffffffu, s, o);
    __shared__ float p[32];
    if ((t & 31) == 0) p[t >> 5] = s;
    __syncthreads();
    if (t < 32) {
        float v = p[t];
        #pragma unroll
        for (int o = 16; o > 0; o >>= 1) v += __shfl_down_sync(0xffffffffu, v, o);
        if (t == 0) g_n = v;
    }
}

// ---------------- finalize 2: new_ema_w, new_codebook, loss ----------------
__global__ void vq_final_cb(const float* __restrict__ ema_w,
                            float* __restrict__ out_ew,
                            float* __restrict__ out_cb,
                            float* __restrict__ out_loss)
{
    int i = blockIdx.x * blockDim.x + threadIdx.x;  // 65536
    float e = 0.99f * ema_w[i] + 0.01f * g_dw[i];
    out_ew[i] = e;
    int k = i >> 6;
    float n = g_n;
    float cs = (g_ncs[k] + 1e-5f) / (n + 1024.0f * 1e-5f) * n;
    out_cb[i] = e / cs;
    if (i == 0) out_loss[0] = g_loss * (1.0f / 8388608.0f);  // 2^-23, exact == /(N*D)
}

// ---------------- launch ----------------
extern "C" void kernel_launch(void* const* d_in, const int* in_sizes, int n_in,
                              void* d_out, int out_size)
{
    const float* z            = (const float*)d_in[0];
    const float* codebook     = (const float*)d_in[1];
    const float* cluster_size = (const float*)d_in[2];
    const float* ema_w        = (const float*)d_in[3];
    float* out = (float*)d_out;

    // output packing: quantized_st | indices | loss | new_codebook | new_cluster_size | new_ema_w
    const size_t OFF_Q    = 0;
    const size_t OFF_IDX  = (size_t)N_TOKENS * CODE_DIM;          // 8388608
    const size_t OFF_LOSS = OFF_IDX + N_TOKENS;                   // 8519680
    const size_t OFF_CB   = OFF_LOSS + 1;                         // 8519681
    const size_t OFF_CS   = OFF_CB + NUM_CODES * CODE_DIM;        // 8585217
    const size_t OFF_EW   = OFF_CS + NUM_CODES;                   // 8586241

    const int smem_bytes = (8192 + 8192 + 128 + 128 + 2048 + 2048) * 4;  // 82944
    cudaFuncSetAttribute(vq_main, cudaFuncAttributeMaxDynamicSharedMemorySize, smem_bytes);

    vq_zero<<<(NUM_CODES * CODE_DIM + 255) / 256, 256>>>();
    vq_main<<<N_TOKENS / 128, 256, smem_bytes>>>(z, codebook, out + OFF_Q, out + OFF_IDX);
    vq_final_cs<<<1, NUM_CODES>>>(cluster_size, out + OFF_CS);
    vq_final_cb<<<(NUM_CODES * CODE_DIM) / 256, 256>>>(ema_w, out + OFF_EW,
                                                       out + OFF_CB, out + OFF_LOSS);
}

// round 5
// speedup vs baseline: 1.3818x; 1.3818x over previous
#include <cuda_runtime.h>
#include <cuda_bf16.h>
#include <cstdint>

#define N_TOKENS  131072
#define CODE_DIM  64
#define NUM_CODES 1024

// ---------------- device scratch (no allocations allowed) ----------------
__device__ float g_counts[NUM_CODES];
__device__ float g_dw[NUM_CODES * CODE_DIM];
__device__ float g_loss;
__device__ float g_ncs[NUM_CODES];
__device__ float g_n;
__device__ __align__(16) __nv_bfloat16 g_cb_hi[NUM_CODES * CODE_DIM];
__device__ __align__(16) __nv_bfloat16 g_cb_lo[NUM_CODES * CODE_DIM];
__device__ float g_cc[NUM_CODES];

// ---------------- prep: zero scratch + split codebook to bf16 hi/lo + cc ----------------
__global__ void vq_prep(const float* __restrict__ codebook) {
    int i = blockIdx.x * blockDim.x + threadIdx.x;   // 65536 threads
    g_dw[i] = 0.0f;
    if (i == 0) g_loss = 0.0f;
    if (i < NUM_CODES) {
        g_counts[i] = 0.0f;
        const float* c = codebook + (size_t)i * CODE_DIM;
        float s0 = 0.0f, s1 = 0.0f;
        #pragma unroll
        for (int k = 0; k < 32; k++) {
            float v = c[k];
            s0 += v * v;
            __nv_bfloat16 h = __float2bfloat16(v);
            g_cb_hi[i * CODE_DIM + k] = h;
            g_cb_lo[i * CODE_DIM + k] = __float2bfloat16(v - __bfloat162float(h));
        }
        #pragma unroll
        for (int k = 32; k < 64; k++) {
            float v = c[k];
            s1 += v * v;
            __nv_bfloat16 h = __float2bfloat16(v);
            g_cb_hi[i * CODE_DIM + k] = h;
            g_cb_lo[i * CODE_DIM + k] = __float2bfloat16(v - __bfloat162float(h));
        }
        g_cc[i] = s0 + s1;
    }
}

// ---------------- mma helpers ----------------
__device__ __forceinline__ void ldsm4(uint32_t (&r)[4], uint32_t addr) {
    asm volatile("ldmatrix.sync.aligned.m8n8.x4.shared.b16 {%0,%1,%2,%3}, [%4];"
                 : "=r"(r[0]), "=r"(r[1]), "=r"(r[2]), "=r"(r[3]) : "r"(addr));
}
__device__ __forceinline__ void mma16816(float (&d)[4], const uint32_t (&a)[4],
                                         const uint32_t* b) {
    asm volatile("mma.sync.aligned.m16n8k16.row.col.f32.bf16.bf16.f32 "
                 "{%0,%1,%2,%3}, {%4,%5,%6,%7}, {%8,%9}, {%0,%1,%2,%3};"
                 : "+f"(d[0]), "+f"(d[1]), "+f"(d[2]), "+f"(d[3])
                 : "r"(a[0]), "r"(a[1]), "r"(a[2]), "r"(a[3]),
                   "r"(b[0]), "r"(b[1]));
}

// exact round-2-style d2 for rescoring near-ties (same op ordering as the
// verified scalar kernel: sequential-FMA dot, h-split sumsq, (zz-2a)+cc).
__device__ __forceinline__ float exact_d2(const float* __restrict__ zrow,
                                          const float* __restrict__ codebook,
                                          int code, float zz) {
    const float* c = codebook + (size_t)code * CODE_DIM;
    float a = 0.0f;
    for (int k = 0; k < CODE_DIM; k++) a = fmaf(zrow[k], c[k], a);
    float c0 = 0.0f, c1 = 0.0f;
    for (int k = 0; k < 32; k++)  { float v = c[k]; c0 += v * v; }
    for (int k = 32; k < 64; k++) { float v = c[k]; c1 += v * v; }
    float cc = c0 + c1;
    return (zz - 2.0f * a) + cc;
}

// top-2 merge: (b1,i1,b2,i2) <- merge with (B1,I1,B2,I2); ties -> smaller index
#define TOP2_MERGE(b1v, i1v, b2v, i2v, B1v, I1v, B2v, I2v) do {               \
    bool _ow = ((B1v) < (b1v)) || ((B1v) == (b1v) && (I1v) < (i1v));          \
    float _f1 = _ow ? (B1v) : (b1v); int _fi = _ow ? (I1v) : (i1v);           \
    float _ls = _ow ? (b1v) : (B1v); int _li = _ow ? (i1v) : (I1v);           \
    float _w2 = _ow ? (B2v) : (b2v); int _wi = _ow ? (i2v) : (I2v);           \
    _wi = _ow ? (I2v) : (i2v);                                                \
    bool _t2 = (_ls < _w2) || (_ls == _w2 && _li < _wi);                      \
    (b1v) = _f1; (i1v) = _fi;                                                 \
    (b2v) = _t2 ? _ls : _w2; (i2v) = _t2 ? _li : _wi;                         \
} while (0)

// ---------------- main: bf16x3 tensor-core screen + argmin + stats ----------------
// Block: 128 tokens x 1024 codes (8 tiles of 128). 8 warps as 2(M) x 4(N),
// warp tile 64 tokens x 32 codes via m16n8k16 bf16 mma, 3 passes (hh, hl, lh).
__global__ __launch_bounds__(256, 1)
void vq_main(const float* __restrict__ z, const float* __restrict__ codebook,
             float* __restrict__ out_q, float* __restrict__ out_idx)
{
    extern __shared__ char smem_raw[];
    float*         zf  = (float*)(smem_raw);                    // [128][65] fp32 z
    __nv_bfloat16* zhi = (__nv_bfloat16*)(smem_raw + 33280);    // [128][72]
    __nv_bfloat16* zlo = (__nv_bfloat16*)(smem_raw + 51712);    // [128][72]
    __nv_bfloat16* chi = (__nv_bfloat16*)(smem_raw + 70144);    // [128][72]
    __nv_bfloat16* clo = (__nv_bfloat16*)(smem_raw + 88576);    // [128][72]
    float*         ccs = (float*)(smem_raw + 107008);           // [128]
    float*         rb1 = (float*)(smem_raw + 107520);           // [128][4]
    float*         rb2 = (float*)(smem_raw + 109568);
    int*           ri1 = (int*)(smem_raw + 111616);
    int*           ri2 = (int*)(smem_raw + 113664);

    const int tid = threadIdx.x;
    const int token0 = blockIdx.x * 128;
    const int lane = tid & 31, wid = tid >> 5;
    const int wm = wid >> 2, wn = wid & 3;
    const int lrow = lane & 7, lmat = lane >> 3;
    const int g = lane >> 2, q4 = lane & 3;

    // ---- load z tile: fp32 copy + bf16 hi/lo split ----
    {
        int r = tid >> 1, h = tid & 1;
        const float4* zp = (const float4*)(z + (size_t)(token0 + r) * CODE_DIM) + h * 8;
        #pragma unroll
        for (int v = 0; v < 8; v++) {
            float4 t4 = zp[v];
            int k = h * 32 + v * 4;
            float vals[4] = {t4.x, t4.y, t4.z, t4.w};
            #pragma unroll
            for (int e = 0; e < 4; e++) {
                float x = vals[e];
                zf[r * 65 + k + e] = x;
                __nv_bfloat16 hh = __float2bfloat16(x);
                zhi[r * 72 + k + e] = hh;
                zlo[r * 72 + k + e] = __float2bfloat16(x - __bfloat162float(hh));
            }
        }
    }

    uint32_t s_zhi = (uint32_t)__cvta_generic_to_shared(zhi);
    uint32_t s_zlo = (uint32_t)__cvta_generic_to_shared(zlo);
    uint32_t s_chi = (uint32_t)__cvta_generic_to_shared(chi);
    uint32_t s_clo = (uint32_t)__cvta_generic_to_shared(clo);

    // ldmatrix lane addressing:
    // A x4: m0 tok0-7/klow, m1 tok8-15/klow, m2 tok0-7/khi, m3 tok8-15/khi
    const int a_row = wm * 64 + (lmat & 1) * 8 + lrow;
    const int a_kof = (lmat >> 1) * 8;
    // B x4: m0 code0-7/klow, m1 code0-7/khi, m2 code8-15/klow, m3 code8-15/khi
    const int b_row = wn * 32 + (lmat >> 1) * 8 + lrow;
    const int b_kof = (lmat & 1) * 8;

    float b1[8], b2[8];
    int   i1[8], i2[8];
    #pragma unroll
    for (int r = 0; r < 8; r++) { b1[r] = 3.4e38f; b2[r] = 3.4e38f; i1[r] = 1 << 30; i2[r] = 1 << 30; }

    for (int ct = 0; ct < 8; ct++) {
        // ---- stage codebook tile (bf16 hi/lo) + cc ----
        {
            int r = tid >> 1, h = tid & 1;
            const uint4* sh = (const uint4*)(g_cb_hi + (size_t)(ct * 128 + r) * CODE_DIM + h * 32);
            const uint4* sl = (const uint4*)(g_cb_lo + (size_t)(ct * 128 + r) * CODE_DIM + h * 32);
            uint4* dh = (uint4*)(chi + r * 72 + h * 32);
            uint4* dl = (uint4*)(clo + r * 72 + h * 32);
            #pragma unroll
            for (int v = 0; v < 4; v++) { dh[v] = sh[v]; dl[v] = sl[v]; }
            if (h == 0) ccs[r] = g_cc[ct * 128 + r];
        }
        __syncthreads();

        float acc[4][4][4];
        #pragma unroll
        for (int mf = 0; mf < 4; mf++)
            #pragma unroll
            for (int nf = 0; nf < 4; nf++)
                #pragma unroll
                for (int e = 0; e < 4; e++) acc[mf][nf][e] = 0.0f;

        #pragma unroll
        for (int kc = 0; kc < 4; kc++) {
            uint32_t ahi[4][4], alo[4][4], bhi[2][4], blo[2][4];
            #pragma unroll
            for (int mf = 0; mf < 4; mf++) {
                uint32_t off = (uint32_t)(((a_row + mf * 16) * 72 + kc * 16 + a_kof) * 2);
                ldsm4(ahi[mf], s_zhi + off);
                ldsm4(alo[mf], s_zlo + off);
            }
            #pragma unroll
            for (int np = 0; np < 2; np++) {
                uint32_t off = (uint32_t)(((b_row + np * 16) * 72 + kc * 16 + b_kof) * 2);
                ldsm4(bhi[np], s_chi + off);
                ldsm4(blo[np], s_clo + off);
            }
            #pragma unroll
            for (int mf = 0; mf < 4; mf++)
                #pragma unroll
                for (int nf = 0; nf < 4; nf++) {
                    const uint32_t* bh = &bhi[nf >> 1][(nf & 1) * 2];
                    const uint32_t* bl = &blo[nf >> 1][(nf & 1) * 2];
                    mma16816(acc[mf][nf], ahi[mf], bh);   // hi*hi
                    mma16816(acc[mf][nf], ahi[mf], bl);   // hi*lo
                    mma16816(acc[mf][nf], alo[mf], bh);   // lo*hi
                }
        }

        // ---- epilogue: screen s = cc - 2*dot, top-2 per token-row ----
        float ccr[8];
        #pragma unroll
        for (int nf = 0; nf < 4; nf++)
            #pragma unroll
            for (int c = 0; c < 2; c++)
                ccr[nf * 2 + c] = ccs[wn * 32 + nf * 8 + q4 * 2 + c];

        #pragma unroll
        for (int mf = 0; mf < 4; mf++)
            #pragma unroll
            for (int rr = 0; rr < 2; rr++) {
                const int row = mf * 2 + rr;
                #pragma unroll
                for (int nf = 0; nf < 4; nf++)
                    #pragma unroll
                    for (int c = 0; c < 2; c++) {
                        float s = fmaf(acc[mf][nf][rr * 2 + c], -2.0f, ccr[nf * 2 + c]);
                        int code = ct * 128 + wn * 32 + nf * 8 + q4 * 2 + c;
                        if (s < b1[row]) {
                            b2[row] = b1[row]; i2[row] = i1[row];
                            b1[row] = s;       i1[row] = code;
                        } else if (s < b2[row]) {
                            b2[row] = s; i2[row] = code;
                        }
                    }
            }
        __syncthreads();
    }

    // ---- quad (lane%4) top-2 merge via shfl ----
    #pragma unroll
    for (int m = 1; m <= 2; m <<= 1) {
        #pragma unroll
        for (int row = 0; row < 8; row++) {
            float B1 = __shfl_xor_sync(0xffffffffu, b1[row], m);
            int   I1 = __shfl_xor_sync(0xffffffffu, i1[row], m);
            float B2 = __shfl_xor_sync(0xffffffffu, b2[row], m);
            int   I2 = __shfl_xor_sync(0xffffffffu, i2[row], m);
            TOP2_MERGE(b1[row], i1[row], b2[row], i2[row], B1, I1, B2, I2);
        }
    }
    if (q4 == 0) {
        #pragma unroll
        for (int row = 0; row < 8; row++) {
            int mf = row >> 1, rr = row & 1;
            int tok = wm * 64 + mf * 16 + rr * 8 + g;
            rb1[tok * 4 + wn] = b1[row]; rb2[tok * 4 + wn] = b2[row];
            ri1[tok * 4 + wn] = i1[row]; ri2[tok * 4 + wn] = i2[row];
        }
    }
    __syncthreads();

    // ---- writer: final merge, rescore near-ties, outputs + scatter stats ----
    float lsum = 0.0f;
    if (tid < 128) {
        const int t = tid;
        float fb1 = rb1[t * 4], fb2 = rb2[t * 4];
        int   fi1 = ri1[t * 4], fi2 = ri2[t * 4];
        #pragma unroll
        for (int w = 1; w < 4; w++) {
            float B1 = rb1[t * 4 + w], B2 = rb2[t * 4 + w];
            int   I1 = ri1[t * 4 + w], I2 = ri2[t * 4 + w];
            TOP2_MERGE(fb1, fi1, fb2, fi2, B1, I1, B2, I2);
        }

        int bi = fi1;
        if (fb2 - fb1 < 0.01f) {
            // near-tie: exact rescore with the verified round-2 arithmetic
            const float* zrow = zf + t * 65;
            float s0 = 0.0f, s1 = 0.0f;
            for (int k = 0; k < 32; k++)  { float v = zrow[k]; s0 += v * v; }
            for (int k = 32; k < 64; k++) { float v = zrow[k]; s1 += v * v; }
            float zz = s0 + s1;
            float da = exact_d2(zrow, codebook, fi1, zz);
            float db = exact_d2(zrow, codebook, fi2, zz);
            if (db < da || (db == da && fi2 < fi1)) bi = fi2;
        }

        const int token = token0 + t;
        out_idx[token] = (float)bi;
        atomicAdd(&g_counts[bi], 1.0f);

        const float4* cb = (const float4*)(codebook + (size_t)bi * CODE_DIM);
        float4* qo = (float4*)(out_q + (size_t)token * CODE_DIM);
        #pragma unroll
        for (int v = 0; v < 16; v++) {
            float4 q = cb[v];
            int k = v * 4;
            float z0 = zf[t * 65 + k + 0];
            float z1 = zf[t * 65 + k + 1];
            float z2 = zf[t * 65 + k + 2];
            float z3 = zf[t * 65 + k + 3];
            float d0 = z0 - q.x, d1 = z1 - q.y, d2 = z2 - q.z, d3 = z3 - q.w;
            lsum += d0 * d0; lsum += d1 * d1; lsum += d2 * d2; lsum += d3 * d3;
            qo[v] = q;
            atomicAdd(&g_dw[bi * CODE_DIM + k + 0], z0);
            atomicAdd(&g_dw[bi * CODE_DIM + k + 1], z1);
            atomicAdd(&g_dw[bi * CODE_DIM + k + 2], z2);
            atomicAdd(&g_dw[bi * CODE_DIM + k + 3], z3);
        }
    }

    // ---- block reduction of commitment-loss partial ----
    #pragma unroll
    for (int o = 16; o > 0; o >>= 1) lsum += __shfl_down_sync(0xffffffffu, lsum, o);
    __shared__ float lpart[8];
    if ((tid & 31) == 0) lpart[tid >> 5] = lsum;
    __syncthreads();
    if (tid == 0) {
        float s = 0.0f;
        #pragma unroll
        for (int w = 0; w < 8; w++) s += lpart[w];
        atomicAdd(&g_loss, s);
    }
}

// ---------------- finalize 1: new_cluster_size + its sum ----------------
__global__ void vq_final_cs(const float* __restrict__ cluster_size,
                            float* __restrict__ out_cs)
{
    int t = threadIdx.x;  // 1024 threads, 1 block
    float ncs = 0.99f * cluster_size[t] + 0.01f * g_counts[t];
    out_cs[t] = ncs;
    g_ncs[t] = ncs;

    float s = ncs;
    #pragma unroll
    for (int o = 16; o > 0; o >>= 1) s += __shfl_down_sync(0xffffffffu, s, o);
    __shared__ float p[32];
    if ((t & 31) == 0) p[t >> 5] = s;
    __syncthreads();
    if (t < 32) {
        float v = p[t];
        #pragma unroll
        for (int o = 16; o > 0; o >>= 1) v += __shfl_down_sync(0xffffffffu, v, o);
        if (t == 0) g_n = v;
    }
}

// ---------------- finalize 2: new_ema_w, new_codebook, loss ----------------
__global__ void vq_final_cb(const float* __restrict__ ema_w,
                            float* __restrict__ out_ew,
                            float* __restrict__ out_cb,
                            float* __restrict__ out_loss)
{
    int i = blockIdx.x * blockDim.x + threadIdx.x;  // 65536
    float e = 0.99f * ema_w[i] + 0.01f * g_dw[i];
    out_ew[i] = e;
    int k = i >> 6;
    float n = g_n;
    float cs = (g_ncs[k] + 1e-5f) / (n + 1024.0f * 1e-5f) * n;
    out_cb[i] = e / cs;
    if (i == 0) out_loss[0] = g_loss * (1.0f / 8388608.0f);  // 2^-23 == 1/(N*D)
}

// ---------------- launch ----------------
extern "C" void kernel_launch(void* const* d_in, const int* in_sizes, int n_in,
                              void* d_out, int out_size)
{
    const float* z            = (const float*)d_in[0];
    const float* codebook     = (const float*)d_in[1];
    const float* cluster_size = (const float*)d_in[2];
    const float* ema_w        = (const float*)d_in[3];
    float* out = (float*)d_out;

    // output packing: quantized_st | indices | loss | new_codebook | new_cluster_size | new_ema_w
    const size_t OFF_Q    = 0;
    const size_t OFF_IDX  = (size_t)N_TOKENS * CODE_DIM;          // 8388608
    const size_t OFF_LOSS = OFF_IDX + N_TOKENS;                   // 8519680
    const size_t OFF_CB   = OFF_LOSS + 1;                         // 8519681
    const size_t OFF_CS   = OFF_CB + NUM_CODES * CODE_DIM;        // 8585217
    const size_t OFF_EW   = OFF_CS + NUM_CODES;                   // 8586241

    const int smem_bytes = 115712;
    cudaFuncSetAttribute(vq_main, cudaFuncAttributeMaxDynamicSharedMemorySize, smem_bytes);

    vq_prep<<<256, 256>>>(codebook);
    vq_main<<<N_TOKENS / 128, 256, smem_bytes>>>(z, codebook, out + OFF_Q, out + OFF_IDX);
    vq_final_cs<<<1, NUM_CODES>>>(cluster_size, out + OFF_CS);
    vq_final_cb<<<(NUM_CODES * CODE_DIM) / 256, 256>>>(ema_w, out + OFF_EW,
                                                       out + OFF_CB, out + OFF_LOSS);
}